// round 13
// baseline (speedup 1.0000x reference)
#include <cuda_runtime.h>
#include <cuda_fp16.h>
#include <cstdint>

// ---------------------------------------------------------------------------
// 2-layer GCN (sm_103: mma.sync HMMA; tcgen05 not available in this build).
//   y1 = z W1 (UNSCALED fp16)  -- ldmatrix m16n8k16 GEMM
//   h  = relu(dinv[d]*(dinv[d]*y1[d] + sum dinv[s]*y1[s]) + b1)
//   y2 = dinv * (h W2) (fp16)
//   out= dinv[d]*(y2[d] + sum y2[s]) + b2
// Overlaps: CSR build ∥ gemm1 (streams);  agg1(h1) ∥ gemm2(h0) by node halves
// (gemm2 rows R read only g_hh rows R; agg1 rows R' write only rows R').
// RULE: __device__ globals only referenced from device code.
// ---------------------------------------------------------------------------

#define MAX_NODES 50048
#define MAX_EDGES 1048576
#define D_IN   256
#define D_HID  256
#define D_OUT  128
#define SCAN_B ((MAX_NODES + 255) / 256)

__device__ float  g_dinv[MAX_NODES];
__device__ int    g_cnt [MAX_NODES];
__device__ int    g_tmp [MAX_NODES];
__device__ int    g_bsum[SCAN_B];
__device__ int    g_rowptr[MAX_NODES + 1];
__device__ int    g_wofs[MAX_NODES];
__device__ int    g_col [MAX_EDGES];
__device__ __half g_y1h[(size_t)MAX_NODES * D_HID];   // UNSCALED z@W1
__device__ __half g_hh [(size_t)MAX_NODES * D_HID];
__device__ __half g_y2h[(size_t)MAX_NODES * D_OUT];   // dinv-scaled h@W2
__device__ __half g_w1t[D_HID * D_IN];
__device__ __half g_w2t[D_OUT * D_HID];

// ---------------------------------------------------------------------------
__device__ __forceinline__ uint32_t smem_u32(const void* p) {
    uint32_t a;
    asm("{ .reg .u64 t; cvta.to.shared.u64 t, %1; cvt.u32.u64 %0, t; }"
        : "=r"(a) : "l"(p));
    return a;
}

__device__ __forceinline__ unsigned f2h2(float lo, float hi) {
    __half2 h = __floats2half2_rn(lo, hi);
    return *reinterpret_cast<unsigned*>(&h);
}

__device__ __forceinline__ void mma_f16(float c[4],
                                        unsigned a0, unsigned a1,
                                        unsigned a2, unsigned a3,
                                        unsigned b0, unsigned b1) {
    asm volatile(
        "mma.sync.aligned.m16n8k16.row.col.f32.f16.f16.f32 "
        "{%0,%1,%2,%3}, {%4,%5,%6,%7}, {%8,%9}, {%0,%1,%2,%3};"
        : "+f"(c[0]), "+f"(c[1]), "+f"(c[2]), "+f"(c[3])
        : "r"(a0), "r"(a1), "r"(a2), "r"(a3), "r"(b0), "r"(b1));
}

__device__ __forceinline__ void ldsm4(uint32_t addr, uint32_t r[4]) {
    asm volatile("ldmatrix.sync.aligned.m8n8.x4.shared.b16 {%0,%1,%2,%3}, [%4];"
                 : "=r"(r[0]), "=r"(r[1]), "=r"(r[2]), "=r"(r[3]) : "r"(addr));
}

// ---------------------------------------------------------------------------
// prep: zero degree counters + pack W1^T, W2^T fp16
// ---------------------------------------------------------------------------
__global__ void prep_kernel(const float* __restrict__ W1,
                            const float* __restrict__ W2, int n_nodes) {
    int i = blockIdx.x * blockDim.x + threadIdx.x;
    if (i < n_nodes) { g_cnt[i] = 0; return; }
    int j = i - n_nodes;
    if (j < D_HID * D_IN) {
        int n = j >> 8, k = j & 255;
        g_w1t[j] = __float2half_rn(W1[k * D_HID + n]);
        return;
    }
    j -= D_HID * D_IN;
    if (j < D_OUT * D_HID) {
        int n = j >> 8, k = j & 255;
        g_w2t[j] = __float2half_rn(W2[k * D_OUT + n]);
    }
}

// ---------------------------------------------------------------------------
// CSR build chain (runs on forked stream)
// ---------------------------------------------------------------------------
__global__ void count_kernel(const int* __restrict__ ei, int n_edges) {
    int e = blockIdx.x * blockDim.x + threadIdx.x;
    if (e < n_edges) atomicAdd(&g_cnt[ei[n_edges + e]], 1);
}
__global__ void scan1_kernel(int n) {
    __shared__ int sh[256];
    int i = blockIdx.x * 256 + threadIdx.x;
    int v = (i < n) ? g_cnt[i] : 0;
    sh[threadIdx.x] = v;
    __syncthreads();
#pragma unroll
    for (int off = 1; off < 256; off <<= 1) {
        int t = (threadIdx.x >= off) ? sh[threadIdx.x - off] : 0;
        __syncthreads();
        sh[threadIdx.x] += t;
        __syncthreads();
    }
    if (i < n) g_tmp[i] = sh[threadIdx.x];
    if (threadIdx.x == 255) g_bsum[blockIdx.x] = sh[255];
}
__global__ void scan2_kernel(int nb) {
    __shared__ int sh[256];
    int t = threadIdx.x;
    int v = (t < nb) ? g_bsum[t] : 0;
    sh[t] = v;
    __syncthreads();
#pragma unroll
    for (int off = 1; off < 256; off <<= 1) {
        int u = (t >= off) ? sh[t - off] : 0;
        __syncthreads();
        sh[t] += u;
        __syncthreads();
    }
    int ex = (t == 0) ? 0 : sh[t - 1];
    if (t < nb) g_bsum[t] = ex;
}
__global__ void scan3_kernel(int n) {
    int i = blockIdx.x * 256 + threadIdx.x;
    if (i < n) {
        int incl = g_tmp[i] + g_bsum[blockIdx.x];
        g_rowptr[i + 1] = incl;
        g_wofs[i] = incl - g_cnt[i];
        g_dinv[i] = rsqrtf((float)(g_cnt[i] + 1));
        if (i == 0) g_rowptr[0] = 0;
    }
}
__global__ void fill_kernel(const int* __restrict__ ei, int n_edges) {
    int e = blockIdx.x * blockDim.x + threadIdx.x;
    if (e < n_edges) {
        int dst = ei[n_edges + e];
        int pos = atomicAdd(&g_wofs[dst], 1);
        g_col[pos] = ei[e];
    }
}

// ---------------------------------------------------------------------------
// fp16 mma GEMM with ldmatrix fragment loads (round-11 proven).
// BM=128, BN=128, BK=32, 256 threads, warp grid 4m x 2n, warp 32x64.
// Smem: row-major 64B pitch, 16B-chunk swizzle chunk^=((row>>1)&3).
// m0: row offset of this launch's block range (node-half pipelining).
// ---------------------------------------------------------------------------
template<bool AHALF, bool SCALE>
__device__ __forceinline__ void gemm_body(const void* __restrict__ Araw,
                                          const __half* __restrict__ Bt,
                                          __half* __restrict__ Yh,
                                          int m0, int M, int Nrow)
{
    __shared__ __align__(128) char sm[32768];
    const uint32_t sb = smem_u32(sm);
    const int tid  = threadIdx.x;
    const int lane = tid & 31;
    const int warp = tid >> 5;
    const int bm   = m0 + blockIdx.x * 128;
    const int bn   = blockIdx.y * 128;
    const int wm   = (warp & 3) * 32;
    const int wn   = (warp >> 2) * 64;

    uint32_t apre[2], bpre[4];
    {
        const int l = lane;
        const int mrl = ((l >> 3) & 1) * 8 + (l & 7);
        const int ah  = (l >> 4) & 1;
#pragma unroll
        for (int mt = 0; mt < 2; mt++) {
            int row = wm + mt * 16 + mrl;
            apre[mt] = sb + row * 64 + ((ah ^ ((row >> 1) & 3)) << 4);
        }
        const int nrl = ((l >> 4) & 1) * 8 + (l & 7);
        const int bh  = (l >> 3) & 1;
#pragma unroll
        for (int p = 0; p < 4; p++) {
            int row = wn + p * 16 + nrl;
            bpre[p] = sb + 16384 + row * 64 + ((bh ^ ((row >> 1) & 3)) << 4);
        }
    }

    uint32_t a_off[2], b_off[2];
    const float*  aF[2];  const __half* aH[2];  bool aok[2];
    const __half* bS[2];
#pragma unroll
    for (int u = 0; u < 2; u++) {
        int c = tid * 2 + u;
        int row = c >> 2, cc = c & 3;
        a_off[u] = (uint32_t)(row * 64 + ((cc ^ ((row >> 1) & 3)) << 4));
        b_off[u] = (uint32_t)(16384 + row * 64 + ((cc ^ ((row >> 1) & 3)) << 4));
        aok[u] = (bm + row) < M;
        if (AHALF) aH[u] = (const __half*)Araw + (size_t)(bm + row) * 256 + cc * 8;
        else       aF[u] = (const float*) Araw + (size_t)(bm + row) * 256 + cc * 8;
        bS[u] = Bt + (size_t)(bn + row) * 256 + cc * 8;
    }

    float acc[2][8][4];
#pragma unroll
    for (int mt = 0; mt < 2; mt++)
#pragma unroll
        for (int nt = 0; nt < 8; nt++)
#pragma unroll
            for (int q = 0; q < 4; q++) acc[mt][nt][q] = 0.0f;

    uint4  pah[2];  float4 paf[2][2];  uint4 pbv[2];

    auto fetch = [&](int t) {
        const int ko = t * 32;
#pragma unroll
        for (int u = 0; u < 2; u++) {
            if (AHALF) {
                pah[u] = aok[u] ? *reinterpret_cast<const uint4*>(aH[u] + ko)
                                : make_uint4(0u, 0u, 0u, 0u);
            } else {
                if (aok[u]) {
                    paf[u][0] = *reinterpret_cast<const float4*>(aF[u] + ko);
                    paf[u][1] = *reinterpret_cast<const float4*>(aF[u] + ko + 4);
                } else {
                    paf[u][0] = paf[u][1] = make_float4(0.f, 0.f, 0.f, 0.f);
                }
            }
            pbv[u] = *reinterpret_cast<const uint4*>(bS[u] + ko);
        }
    };
    auto store = [&](int buf) {
        const uint32_t bo = (uint32_t)buf * 8192;
#pragma unroll
        for (int u = 0; u < 2; u++) {
            uint4 w;
            if (AHALF) {
                w = pah[u];
            } else {
                w.x = f2h2(paf[u][0].x, paf[u][0].y);
                w.y = f2h2(paf[u][0].z, paf[u][0].w);
                w.z = f2h2(paf[u][1].x, paf[u][1].y);
                w.w = f2h2(paf[u][1].z, paf[u][1].w);
            }
            *reinterpret_cast<uint4*>(sm + bo + a_off[u]) = w;
            *reinterpret_cast<uint4*>(sm + bo + b_off[u]) = pbv[u];
        }
    };

    fetch(0);
    store(0);
    __syncthreads();

    const int nk = 256 / 32;
    int cur = 0;
    for (int t = 0; t < nk; t++) {
        if (t + 1 < nk) fetch(t + 1);

        const uint32_t bo = (uint32_t)cur * 8192;
#pragma unroll
        for (int ks = 0; ks < 2; ks++) {
            const uint32_t kx = (uint32_t)ks << 5;
            uint32_t af[2][4];
#pragma unroll
            for (int mt = 0; mt < 2; mt++)
                ldsm4((apre[mt] + bo) ^ kx, af[mt]);
            uint32_t bf[8][2];
#pragma unroll
            for (int p = 0; p < 4; p++) {
                uint32_t b4[4];
                ldsm4((bpre[p] + bo) ^ kx, b4);
                bf[2 * p][0] = b4[0]; bf[2 * p][1] = b4[1];
                bf[2 * p + 1][0] = b4[2]; bf[2 * p + 1][1] = b4[3];
            }
#pragma unroll
            for (int mt = 0; mt < 2; mt++)
#pragma unroll
                for (int nt = 0; nt < 8; nt++)
                    mma_f16(acc[mt][nt],
                            af[mt][0], af[mt][1], af[mt][2], af[mt][3],
                            bf[nt][0], bf[nt][1]);
        }

        if (t + 1 < nk) {
            store(cur ^ 1);
            __syncthreads();
            cur ^= 1;
        }
    }

    const int g = lane >> 2, tig = lane & 3;
#pragma unroll
    for (int mt = 0; mt < 2; mt++) {
        int r0 = bm + wm + mt * 16 + g;
        int r1 = r0 + 8;
        float s0 = 1.0f, s1 = 1.0f;
        if (SCALE) {
            s0 = (r0 < M) ? g_dinv[r0] : 0.0f;
            s1 = (r1 < M) ? g_dinv[r1] : 0.0f;
        }
#pragma unroll
        for (int nt = 0; nt < 8; nt++) {
            int c = bn + wn + nt * 8 + 2 * tig;
            if (r0 < M)
                *reinterpret_cast<__half2*>(Yh + (size_t)r0 * Nrow + c) =
                    __floats2half2_rn(s0 * acc[mt][nt][0], s0 * acc[mt][nt][1]);
            if (r1 < M)
                *reinterpret_cast<__half2*>(Yh + (size_t)r1 * Nrow + c) =
                    __floats2half2_rn(s1 * acc[mt][nt][2], s1 * acc[mt][nt][3]);
        }
    }
}

__global__ __launch_bounds__(256) void gemm1_kernel(const float* __restrict__ z,
                                                    int M)
{
    gemm_body<false, false>(z, g_w1t, g_y1h, 0, M, D_HID);
}

__global__ __launch_bounds__(256) void gemm2_kernel(int m0, int M)
{
    gemm_body<true, true>(g_hh, g_w2t, g_y2h, m0, M, D_OUT);
}

// ---------------------------------------------------------------------------
// CSR aggregation (round-11 proven; agg1 applies dinv[s] per edge).
// agg1 takes a node range [node0, node_end) for half-pipelining.
// ---------------------------------------------------------------------------
__device__ __forceinline__ void h8_fma(float a[8], uint4 u, float d) {
    float2 f;
    f = __half22float2(*reinterpret_cast<const __half2*>(&u.x));
    a[0] = fmaf(d, f.x, a[0]); a[1] = fmaf(d, f.y, a[1]);
    f = __half22float2(*reinterpret_cast<const __half2*>(&u.y));
    a[2] = fmaf(d, f.x, a[2]); a[3] = fmaf(d, f.y, a[3]);
    f = __half22float2(*reinterpret_cast<const __half2*>(&u.z));
    a[4] = fmaf(d, f.x, a[4]); a[5] = fmaf(d, f.y, a[5]);
    f = __half22float2(*reinterpret_cast<const __half2*>(&u.w));
    a[6] = fmaf(d, f.x, a[6]); a[7] = fmaf(d, f.y, a[7]);
}
__device__ __forceinline__ void h4_add(float a[4], uint2 u) {
    float2 f;
    f = __half22float2(*reinterpret_cast<const __half2*>(&u.x));
    a[0] += f.x; a[1] += f.y;
    f = __half22float2(*reinterpret_cast<const __half2*>(&u.y));
    a[2] += f.x; a[3] += f.y;
}

__global__ __launch_bounds__(256) void agg1_kernel(const float* __restrict__ bias,
                                                   int node0, int node_end)
{
    const int node = node0 + ((blockIdx.x * blockDim.x + threadIdx.x) >> 5);
    const int lane = threadIdx.x & 31;
    if (node >= node_end) return;

    const uint4* Yv = reinterpret_cast<const uint4*>(g_y1h);
    const float sself = g_dinv[node];

    float a[8];
    {
        uint4 u = Yv[(size_t)node * 32 + lane];
        float2 f;
        f = __half22float2(*reinterpret_cast<const __half2*>(&u.x));
        a[0] = sself * f.x; a[1] = sself * f.y;
        f = __half22float2(*reinterpret_cast<const __half2*>(&u.y));
        a[2] = sself * f.x; a[3] = sself * f.y;
        f = __half22float2(*reinterpret_cast<const __half2*>(&u.z));
        a[4] = sself * f.x; a[5] = sself * f.y;
        f = __half22float2(*reinterpret_cast<const __half2*>(&u.w));
        a[6] = sself * f.x; a[7] = sself * f.y;
    }
    const int e0 = g_rowptr[node];
    const int e1 = g_rowptr[node + 1];

    int e = e0;
    if (e + 1 < e1) {
        int s0 = g_col[e], s1 = g_col[e + 1];
        uint4 v0 = Yv[(size_t)s0 * 32 + lane];
        uint4 v1 = Yv[(size_t)s1 * 32 + lane];
        float d0 = g_dinv[s0], d1 = g_dinv[s1];
        e += 2;
        for (; e + 1 < e1; e += 2) {
            int n0 = g_col[e], n1 = g_col[e + 1];
            uint4 w0 = Yv[(size_t)n0 * 32 + lane];
            uint4 w1 = Yv[(size_t)n1 * 32 + lane];
            float dd0 = g_dinv[n0], dd1 = g_dinv[n1];
            h8_fma(a, v0, d0); h8_fma(a, v1, d1);
            v0 = w0; v1 = w1; d0 = dd0; d1 = dd1;
        }
        h8_fma(a, v0, d0); h8_fma(a, v1, d1);
    }
    if (e < e1) {
        int s = g_col[e];
        h8_fma(a, Yv[(size_t)s * 32 + lane], g_dinv[s]);
    }

    const float4* bv = reinterpret_cast<const float4*>(bias);
    float4 b0 = bv[lane * 2], b1 = bv[lane * 2 + 1];
    float o[8];
    o[0] = fmaxf(fmaf(sself, a[0], b0.x), 0.f);
    o[1] = fmaxf(fmaf(sself, a[1], b0.y), 0.f);
    o[2] = fmaxf(fmaf(sself, a[2], b0.z), 0.f);
    o[3] = fmaxf(fmaf(sself, a[3], b0.w), 0.f);
    o[4] = fmaxf(fmaf(sself, a[4], b1.x), 0.f);
    o[5] = fmaxf(fmaf(sself, a[5], b1.y), 0.f);
    o[6] = fmaxf(fmaf(sself, a[6], b1.z), 0.f);
    o[7] = fmaxf(fmaf(sself, a[7], b1.w), 0.f);
    uint4 w;
    w.x = f2h2(o[0], o[1]); w.y = f2h2(o[2], o[3]);
    w.z = f2h2(o[4], o[5]); w.w = f2h2(o[6], o[7]);
    reinterpret_cast<uint4*>(g_hh + (size_t)node * 256)[lane] = w;
}

__global__ __launch_bounds__(256) void agg2_kernel(float* __restrict__ out,
                                                   const float* __restrict__ bias,
                                                   int n_nodes)
{
    const int node = (blockIdx.x * blockDim.x + threadIdx.x) >> 5;
    const int lane = threadIdx.x & 31;
    if (node >= n_nodes) return;

    const uint2* Yv = reinterpret_cast<const uint2*>(g_y2h);
    float a[4];
    {
        uint2 u = Yv[(size_t)node * 32 + lane];
        float2 f;
        f = __half22float2(*reinterpret_cast<const __half2*>(&u.x));
        a[0] = f.x; a[1] = f.y;
        f = __half22float2(*reinterpret_cast<const __half2*>(&u.y));
        a[2] = f.x; a[3] = f.y;
    }
    const int e0 = g_rowptr[node];
    const int e1 = g_rowptr[node + 1];

    int e = e0;
    if (e + 1 < e1) {
        uint2 v0 = Yv[(size_t)g_col[e]     * 32 + lane];
        uint2 v1 = Yv[(size_t)g_col[e + 1] * 32 + lane];
        e += 2;
        for (; e + 1 < e1; e += 2) {
            uint2 w0 = Yv[(size_t)g_col[e]     * 32 + lane];
            uint2 w1 = Yv[(size_t)g_col[e + 1] * 32 + lane];
            h4_add(a, v0); h4_add(a, v1);
            v0 = w0; v1 = w1;
        }
        h4_add(a, v0); h4_add(a, v1);
    }
    if (e < e1) h4_add(a, Yv[(size_t)g_col[e] * 32 + lane]);

    const float s = g_dinv[node];
    float4 b = reinterpret_cast<const float4*>(bias)[lane];
    float4 o;
    o.x = fmaf(s, a[0], b.x);
    o.y = fmaf(s, a[1], b.y);
    o.z = fmaf(s, a[2], b.z);
    o.w = fmaf(s, a[3], b.w);
    reinterpret_cast<float4*>(out + (size_t)node * 128)[lane] = o;
}

// ---------------------------------------------------------------------------
extern "C" void kernel_launch(void* const* d_in, const int* in_sizes, int n_in,
                              void* d_out, int out_size)
{
    const float* z   = (const float*)d_in[0];
    const int*   ei  = (const int*)  d_in[1];
    const float* W1  = (const float*)d_in[2];
    const float* b1  = (const float*)d_in[3];
    const float* W2  = (const float*)d_in[4];
    const float* b2  = (const float*)d_in[5];
    float* out = (float*)d_out;

    const int n_nodes = in_sizes[0] / D_IN;
    const int n_edges = in_sizes[1] / 2;
    const int T   = 256;
    const int nbN = (n_nodes + T - 1) / T;
    const int nbE = (n_edges + T - 1) / T;

    // one-time side-stream + events (host resources, no device allocation)
    static cudaStream_t s2 = nullptr;
    static cudaEvent_t evF1 = nullptr, evJ1 = nullptr, evF2 = nullptr, evJ2 = nullptr;
    if (s2 == nullptr) {
        cudaStreamCreateWithFlags(&s2, cudaStreamNonBlocking);
        cudaEventCreateWithFlags(&evF1, cudaEventDisableTiming);
        cudaEventCreateWithFlags(&evJ1, cudaEventDisableTiming);
        cudaEventCreateWithFlags(&evF2, cudaEventDisableTiming);
        cudaEventCreateWithFlags(&evJ2, cudaEventDisableTiming);
    }

    const int prepN = n_nodes + D_HID * D_IN + D_OUT * D_HID;
    prep_kernel<<<(prepN + T - 1) / T, T>>>(W1, W2, n_nodes);

    // ---- fork 1: CSR build on s2, gemm1 on main ----
    cudaEventRecord(evF1, 0);
    cudaStreamWaitEvent(s2, evF1, 0);

    count_kernel<<<nbE, T, 0, s2>>>(ei, n_edges);
    scan1_kernel<<<nbN, T, 0, s2>>>(n_nodes);
    scan2_kernel<<<1,   T, 0, s2>>>(nbN);
    scan3_kernel<<<nbN, T, 0, s2>>>(n_nodes);
    fill_kernel <<<nbE, T, 0, s2>>>(ei, n_edges);
    cudaEventRecord(evJ1, s2);

    const unsigned gx = (unsigned)((n_nodes + 127) / 128);
    gemm1_kernel<<<dim3(gx, D_HID / 128), T>>>(z, n_nodes);

    cudaStreamWaitEvent(0, evJ1, 0);

    // ---- layer-boundary half pipeline ----
    // halves: h0 = [0, n0), h1 = [n0, n_nodes), n0 multiple of 128
    const int n0  = ((n_nodes / 2) + 127) & ~127;
    const int n1c = n_nodes - n0;
    const unsigned gx0 = (unsigned)(n0 / 128);
    const unsigned gx1 = (unsigned)((n1c + 127) / 128);
    const unsigned aggB0 = (unsigned)(((long long)n0  * 32 + T - 1) / T);
    const unsigned aggB1 = (unsigned)(((long long)n1c * 32 + T - 1) / T);

    // agg1 half 0 on main
    agg1_kernel<<<aggB0, T>>>(b1, 0, n0);

    // fork 2: agg1 half 1 on s2, gemm2 half 0 on main
    cudaEventRecord(evF2, 0);
    cudaStreamWaitEvent(s2, evF2, 0);
    agg1_kernel<<<aggB1, T, 0, s2>>>(b1, n0, n_nodes);
    cudaEventRecord(evJ2, s2);

    gemm2_kernel<<<dim3(gx0, 1), T>>>(0, n_nodes);

    // join, then gemm2 half 1
    cudaStreamWaitEvent(0, evJ2, 0);
    gemm2_kernel<<<dim3(gx1, 1), T>>>(n0, n_nodes);

    // agg2 (needs full y2)
    const unsigned aggB = (unsigned)(((long long)n_nodes * 32 + T - 1) / T);
    agg2_kernel<<<aggB, T>>>(out, b2, n_nodes);
}